// round 11
// baseline (speedup 1.0000x reference)
#include <cuda_runtime.h>
#include <float.h>

#define VX 64
#define NB 8
#define NP 32
#define PE 32
#define EPSF 1e-8f
#define NTHREADS 512
#define NWARPS 16

__device__ __forceinline__ float ex2_approx(float x) {
    float r; asm("ex2.approx.ftz.f32 %0, %1;" : "=f"(r) : "f"(x)); return r;
}
__device__ __forceinline__ float rcp_approx(float x) {
    float r; asm("rcp.approx.ftz.f32 %0, %1;" : "=f"(r) : "f"(x)); return r;
}

// Block: one (batch b, row y), 16 warps, 2 pixels/lane.
// Work unit = HALF polygon (16 edges): 2*nv tasks dealt round-robin to 16
// warps -> critical path ceil(2nv/16) tasks (kills the nv>16 2x cliff).
// Phase 2 computes ONLY raw partial min_d2 per task (no sqrt/sigmoid/sign).
// Phase 3 merges task halves, classifies with the precomputed per-poly
// 64-bit parity masks, and uses max_p sigmoid(-k*s_p) = sigmoid(-k*min_p s_p)
// so there is exactly ONE sqrt + ONE sigmoid per pixel in the whole kernel.
__global__ __launch_bounds__(NTHREADS, 2) void extrusion_kernel(
    const float* __restrict__ polygons,   // [B][N][P][2]
    const float* __restrict__ attributes, // [B][4]
    const float* __restrict__ validity,   // [B][N]
    float* __restrict__ out)              // [B][V][V][V]
{
    __shared__ __align__(16) float4 sA[NP * PE];     // x0, exi, syi, ey
    __shared__ __align__(16) float2 sC[NP * PE];     // ex, vy
    __shared__ __align__(16) float  sTask[2 * NP][VX]; // per-task partial min_d2
    __shared__ __align__(16) float  sComb[VX];
    __shared__ unsigned sParLo[NP], sParHi[NP];      // per-poly parity bitmask
    __shared__ int sIdx[NP];
    __shared__ int sV;

    const int b   = blockIdx.x & 7;        // low bits: mix batches across SMs
    const int row = blockIdx.x >> 3;
    const int tid = threadIdx.x;
    const float py = (float)row * (1.0f / 63.0f);

    // ---- Phase 0: h + early zero stores (independent of SDF) ----
    int h = (int)floorf(attributes[b * 4 + 0] * (float)VX);
    h = max(1, min(VX, h));
    float* out_base = out + (size_t)b * VX * VX * VX + (size_t)row * VX;
    const float4 zero4 = make_float4(0.f, 0.f, 0.f, 0.f);
    for (int i = h * 16 + tid; i < VX * 16; i += NTHREADS) {
        const int z = i >> 4;
        const int q = i & 15;
        ((float4*)(out_base + (size_t)z * VX * VX))[q] = zero4;
    }

    // ---- Phase 1a: validity compaction (warp 0) ----
    if (tid < 32) {
        const bool valid = validity[b * NP + tid] >= 0.5f;
        const unsigned m = __ballot_sync(0xffffffffu, valid);
        if (valid) {
            const int pos = __popc(m & ((1u << tid) - 1u));
            sIdx[pos] = tid;
        }
        if (tid == 0) sV = __popc(m);
    }

    // ---- Phase 1b: edge precompute + per-poly parity masks (fast math) ----
    // warp w (0..15), lane e handles edge e of polys {w, w+16}.
    const float2* pv = (const float2*)(polygons + (size_t)b * NP * PE * 2);
    {
        const int w = tid >> 5;
        const int e = tid & 31;
        const int e1 = (e + 1) & 31;
        #pragma unroll
        for (int k = 0; k < 2; k++) {
            const int n = w + 16 * k;
            const float2 v0 = pv[n * PE + e];
            const float2 v1 = pv[n * PE + e1];
            const float ex = v1.x - v0.x;
            const float ey = v1.y - v0.y;
            const float inv = rcp_approx(fmaf(ex, ex, fmaf(ey, ey, EPSF)));
            const float vy  = py - v0.y;
            sA[n * PE + e] = make_float4(v0.x, ex * inv, (vy * ey) * inv, ey);
            sC[n * PE + e] = make_float2(ex, vy);
            // crossing threshold -> prefix bitmask over the 64 pixel columns
            const bool ycr = (fminf(v0.y, v1.y) <= py) && (fmaxf(v0.y, v1.y) > py);
            const float interx = fmaf(ex, __fdividef(vy, ey + EPSF), v0.x);
            const float cxthr = ycr ? interx : -FLT_MAX;
            float t = fminf(fmaxf(cxthr * 63.0f, -1.0f), 65.0f);
            int idx = (int)ceilf(t);
            idx = max(0, min(64, idx));
            const unsigned long long m64 =
                (idx >= 64) ? ~0ull : ((1ull << idx) - 1ull);
            const unsigned lo = __reduce_xor_sync(0xffffffffu, (unsigned)m64);
            const unsigned hi = __reduce_xor_sync(0xffffffffu, (unsigned)(m64 >> 32));
            if (e == 0) { sParLo[n] = lo; sParHi[n] = hi; }
        }
    }
    __syncthreads();

    // ---- Phase 2: raw partial min_d2 per half-poly task, 2 px/lane ----
    const int lane = tid & 31;
    const int g    = tid >> 5;
    const float pxa = (float)lane        * (1.0f / 63.0f);
    const float pxb = (float)(lane + 32) * (1.0f / 63.0f);
    const int nv = sV;
    const int ntask = 2 * nv;

    #pragma unroll 1
    for (int j = g; j < ntask; j += NWARPS) {     // <=2 iters when nv<=16
        const int n  = sIdx[j >> 1];
        const int e0 = (j & 1) << 4;              // 0 or 16
        const float4* A4 = sA + n * PE + e0;
        const float2* C2 = sC + n * PE + e0;
        float mA0 = FLT_MAX, mA1 = FLT_MAX;       // even/odd chains, pixel a
        float mB0 = FLT_MAX, mB1 = FLT_MAX;       // even/odd chains, pixel b
        #pragma unroll
        for (int e = 0; e < 16; e += 2) {
            {
                const float4 a = A4[e];
                const float2 c = C2[e];
                const float vxa = pxa - a.x;
                const float vxb = pxb - a.x;
                const float ta = __saturatef(fmaf(vxa, a.y, a.z));
                const float tb = __saturatef(fmaf(vxb, a.y, a.z));
                const float dxa = fmaf(-ta, c.x, vxa);
                const float dxb = fmaf(-tb, c.x, vxb);
                const float dya = fmaf(-ta, a.w, c.y);
                const float dyb = fmaf(-tb, a.w, c.y);
                mA0 = fminf(mA0, fmaf(dya, dya, dxa * dxa));
                mB0 = fminf(mB0, fmaf(dyb, dyb, dxb * dxb));
            }
            {
                const float4 a = A4[e + 1];
                const float2 c = C2[e + 1];
                const float vxa = pxa - a.x;
                const float vxb = pxb - a.x;
                const float ta = __saturatef(fmaf(vxa, a.y, a.z));
                const float tb = __saturatef(fmaf(vxb, a.y, a.z));
                const float dxa = fmaf(-ta, c.x, vxa);
                const float dxb = fmaf(-tb, c.x, vxb);
                const float dya = fmaf(-ta, a.w, c.y);
                const float dyb = fmaf(-tb, a.w, c.y);
                mA1 = fminf(mA1, fmaf(dya, dya, dxa * dxa));
                mB1 = fminf(mB1, fmaf(dyb, dyb, dxb * dxb));
            }
        }
        sTask[j][lane]      = fminf(mA0, mA1);
        sTask[j][lane + 32] = fminf(mB0, mB1);
    }
    __syncthreads();

    // ---- Phase 3: per-pixel merge across polys; ONE sqrt + ONE sigmoid ----
    if (tid < VX) {
        const unsigned sh = tid & 31;
        const bool hiHalf = tid >= 32;
        float m_in  = 0.0f;        // max d2 among inside polys
        float m_out = FLT_MAX;     // min d2 among outside polys
        #pragma unroll 1
        for (int p = 0; p < nv; p++) {
            const int n = sIdx[p];
            const float m = fminf(sTask[2 * p][tid], sTask[2 * p + 1][tid]);
            const unsigned mask = hiHalf ? sParHi[n] : sParLo[n];
            const bool inside = (mask >> sh) & 1u;
            m_in  = inside ? fmaxf(m_in, m)  : m_in;
            m_out = inside ? m_out           : fminf(m_out, m);
        }
        const bool any_in = m_in > 0.0f;
        const float sdf = any_in ? -sqrtf(m_in) : sqrtf(m_out);
        // sigmoid(-100*sdf) = 1/(1 + 2^(144.27*sdf))
        sComb[tid] = rcp_approx(1.0f + ex2_approx(sdf * 144.269504f));
    }
    __syncthreads();

    // ---- Phase 4: store the z < h slabs ----
    const float4* comb4 = (const float4*)sComb;
    for (int i = tid; i < h * 16; i += NTHREADS) {
        const int z = i >> 4;
        const int q = i & 15;
        ((float4*)(out_base + (size_t)z * VX * VX))[q] = comb4[q];
    }
}

extern "C" void kernel_launch(void* const* d_in, const int* in_sizes, int n_in,
                              void* d_out, int out_size) {
    const float* polygons   = (const float*)d_in[0];
    const float* attributes = (const float*)d_in[1];
    const float* validity   = (const float*)d_in[2];
    float* out = (float*)d_out;
    (void)in_sizes; (void)n_in; (void)out_size;

    extrusion_kernel<<<NB * VX, NTHREADS>>>(polygons, attributes, validity, out);
}

// round 12
// speedup vs baseline: 1.0497x; 1.0497x over previous
#include <cuda_runtime.h>
#include <float.h>

#define VX 64
#define NB 8
#define NP 32
#define PE 32
#define EPSF 1e-8f
#define NQ 4                 // poly quarters
#define NPQ (NP / NQ)        // 8 polys per quarter

// Scratch: per-quarter partial combined rows. Written disjointly by kernel A,
// reduced by kernel B. __device__ global (no allocation).
__device__ float g_scratch[NQ * NB * VX * VX];

__device__ __forceinline__ float ex2_approx(float x) {
    float r; asm("ex2.approx.ftz.f32 %0, %1;" : "=f"(r) : "f"(x)); return r;
}
__device__ __forceinline__ float rcp_approx(float x) {
    float r; asm("rcp.approx.ftz.f32 %0, %1;" : "=f"(r) : "f"(x)); return r;
}

// ---------------- Kernel A: SDF compute, 2048 blocks (b, row, quarter) -------
// 128 threads = 4 warps. Block owns 8 polys; valid ones are compacted and
// dealt to the 4 warps (typically 1 poly/warp). Parity precomputed as 64-bit
// pixel mask per poly, so the 32-edge loop has zero predicate work.
__global__ __launch_bounds__(128, 8) void sdf_kernel(
    const float* __restrict__ polygons,   // [B][N][P][2]
    const float* __restrict__ validity)   // [B][N]
{
    __shared__ __align__(16) float4 sA[NPQ * PE];   // x0, exi, syi, ey
    __shared__ __align__(16) float2 sC[NPQ * PE];   // ex, vy
    __shared__ __align__(16) float  sPartial[4][VX];
    __shared__ unsigned sParLo[NPQ], sParHi[NPQ];
    __shared__ int sIdx[NPQ];
    __shared__ int sV;

    const int bid = blockIdx.x;
    const int q   = bid & 3;             // low bits mix quarters/batches on SMs
    const int b   = (bid >> 2) & 7;
    const int row = bid >> 5;
    const int tid = threadIdx.x;
    const float py = (float)row * (1.0f / 63.0f);

    // ---- validity compaction over this quarter's 8 polys ----
    if (tid < 32) {
        const bool valid = (tid < NPQ) &&
                           (validity[b * NP + q * NPQ + tid] >= 0.5f);
        const unsigned m = __ballot_sync(0xffffffffu, valid);
        if (valid) {
            const int pos = __popc(m & ((1u << tid) - 1u));
            sIdx[pos] = tid;              // local poly index 0..7
        }
        if (tid == 0) sV = __popc(m);
    }

    // ---- edge precompute + parity masks: warp w -> local polys {w, w+4} ----
    const float2* pv = (const float2*)(polygons + ((size_t)b * NP + q * NPQ) * PE * 2);
    {
        const int w = tid >> 5;
        const int e = tid & 31;
        const int e1 = (e + 1) & 31;
        #pragma unroll
        for (int k = 0; k < 2; k++) {
            const int n = w + 4 * k;      // local poly
            const float2 v0 = pv[n * PE + e];
            const float2 v1 = pv[n * PE + e1];
            const float ex = v1.x - v0.x;
            const float ey = v1.y - v0.y;
            const float inv = rcp_approx(fmaf(ex, ex, fmaf(ey, ey, EPSF)));
            const float vy  = py - v0.y;
            sA[n * PE + e] = make_float4(v0.x, ex * inv, (vy * ey) * inv, ey);
            sC[n * PE + e] = make_float2(ex, vy);
            const bool ycr = (fminf(v0.y, v1.y) <= py) && (fmaxf(v0.y, v1.y) > py);
            const float interx = fmaf(ex, __fdividef(vy, ey + EPSF), v0.x);
            const float cxthr = ycr ? interx : -FLT_MAX;
            float t = fminf(fmaxf(cxthr * 63.0f, -1.0f), 65.0f);
            int idx = (int)ceilf(t);
            idx = max(0, min(64, idx));
            const unsigned long long m64 =
                (idx >= 64) ? ~0ull : ((1ull << idx) - 1ull);
            const unsigned lo = __reduce_xor_sync(0xffffffffu, (unsigned)m64);
            const unsigned hi = __reduce_xor_sync(0xffffffffu, (unsigned)(m64 >> 32));
            if (e == 0) { sParLo[n] = lo; sParHi[n] = hi; }
        }
    }
    __syncthreads();

    // ---- SDF + sigmoid + max: warp g takes compacted polys g, g+4, ... ----
    const int lane = tid & 31;
    const int g    = tid >> 5;
    const float pxa = (float)lane        * (1.0f / 63.0f);
    const float pxb = (float)(lane + 32) * (1.0f / 63.0f);
    const int nv = sV;

    float best_a = 0.0f, best_b = 0.0f;
    #pragma unroll 1
    for (int j = g; j < nv; j += 4) {      // typically 1 iteration
        const int n = sIdx[j];
        const unsigned sign_a = ((sParLo[n] >> lane) & 1u) << 31;
        const unsigned sign_b = ((sParHi[n] >> lane) & 1u) << 31;
        float min_a = FLT_MAX, min_b = FLT_MAX;
        const float4* A4 = sA + n * PE;
        const float2* C2 = sC + n * PE;
        #pragma unroll
        for (int e = 0; e < PE; e++) {
            const float4 a = A4[e];        // x0, exi, syi, ey
            const float2 c = C2[e];        // ex, vy
            const float vxa = pxa - a.x;
            const float vxb = pxb - a.x;
            const float ta = __saturatef(fmaf(vxa, a.y, a.z));
            const float tb = __saturatef(fmaf(vxb, a.y, a.z));
            const float dxa = fmaf(-ta, c.x, vxa);
            const float dxb = fmaf(-tb, c.x, vxb);
            const float dya = fmaf(-ta, a.w, c.y);
            const float dyb = fmaf(-tb, a.w, c.y);
            min_a = fminf(min_a, fmaf(dya, dya, dxa * dxa));
            min_b = fminf(min_b, fmaf(dyb, dyb, dxb * dxb));
        }
        const float sa = __uint_as_float(__float_as_uint(sqrtf(min_a)) ^ sign_a);
        const float sb = __uint_as_float(__float_as_uint(sqrtf(min_b)) ^ sign_b);
        // sigmoid(-100*s) = 1/(1 + 2^(144.27*s))
        best_a = fmaxf(best_a, rcp_approx(1.0f + ex2_approx(sa * 144.269504f)));
        best_b = fmaxf(best_b, rcp_approx(1.0f + ex2_approx(sb * 144.269504f)));
    }
    sPartial[g][lane]      = best_a;
    sPartial[g][lane + 32] = best_b;
    __syncthreads();

    // ---- 4-way reduce and write this quarter's partial row ----
    if (tid < VX) {
        const float m = fmaxf(fmaxf(sPartial[0][tid], sPartial[1][tid]),
                              fmaxf(sPartial[2][tid], sPartial[3][tid]));
        g_scratch[((q * NB + b) * VX + row) * VX + tid] = m;
    }
}

// ---------------- Kernel B: quarter-merge + depth expansion (BW-bound) ------
__global__ __launch_bounds__(256) void expand_kernel(
    const float* __restrict__ attributes, // [B][4]
    float* __restrict__ out)              // [B][V][V][V]
{
    __shared__ __align__(16) float sComb[VX];

    const int b   = blockIdx.x & 7;
    const int row = blockIdx.x >> 3;
    const int tid = threadIdx.x;

    if (tid < VX) {
        const size_t base = ((size_t)b * VX + row) * VX + tid;
        float m = g_scratch[base];
        #pragma unroll
        for (int q = 1; q < NQ; q++)
            m = fmaxf(m, g_scratch[(size_t)q * NB * VX * VX + base]);
        sComb[tid] = m;
    }
    __syncthreads();

    int h = (int)floorf(attributes[b * 4 + 0] * (float)VX);
    h = max(1, min(VX, h));

    const float4* comb4 = (const float4*)sComb;
    float* out_base = out + (size_t)b * VX * VX * VX + (size_t)row * VX;
    const float4 zero4 = make_float4(0.f, 0.f, 0.f, 0.f);
    #pragma unroll
    for (int i = tid; i < VX * 16; i += 256) {
        const int z = i >> 4;
        const int k = i & 15;
        ((float4*)(out_base + (size_t)z * VX * VX))[k] = (z < h) ? comb4[k] : zero4;
    }
}

extern "C" void kernel_launch(void* const* d_in, const int* in_sizes, int n_in,
                              void* d_out, int out_size) {
    const float* polygons   = (const float*)d_in[0];
    const float* attributes = (const float*)d_in[1];
    const float* validity   = (const float*)d_in[2];
    float* out = (float*)d_out;
    (void)in_sizes; (void)n_in; (void)out_size;

    sdf_kernel<<<NB * VX * NQ, 128>>>(polygons, validity);
    expand_kernel<<<NB * VX, 256>>>(attributes, out);
}